// round 3
// baseline (speedup 1.0000x reference)
#include <cuda_runtime.h>

// ---------------- problem constants ----------------
// B=2, C=21, H=W=512, pooled 128x128, K=11 (radius 5), 5 steps, pad=(0,0)

// ---------------- scratch (device globals; no mallocs allowed) ----------------
__device__ float g_unary[11010048];   // [2][21][512][512]
__device__ float g_qb[688128];        // [2][21][128][128]
__device__ float g_msg[688128];       // [2][21][128][128]
__device__ float g_kcomb[3964928];    // [2][121][128][128]  (j-major)
__device__ float g_rgbp[98304];       // [2][3][128][128]    (already /13)

// ---------------- backbone 3x3 conv, 3 -> 21 ----------------
__global__ void k_conv(const float* __restrict__ x, const float* __restrict__ w,
                       const float* __restrict__ bias) {
  __shared__ float xs[3][10][34];
  __shared__ float ws[567];
  __shared__ float bs[21];
  const int b  = blockIdx.z;
  const int x0 = blockIdx.x * 32, y0 = blockIdx.y * 8;
  const int tx = threadIdx.x, ty = threadIdx.y;
  const int tid = ty * 32 + tx;
  for (int i = tid; i < 567; i += 256) ws[i] = w[i];
  if (tid < 21) bs[tid] = bias[tid];
  for (int i = tid; i < 3 * 10 * 34; i += 256) {
    int c = i / 340, rem = i % 340, yy = rem / 34, xx = rem % 34;
    int gy = y0 + yy - 1, gx = x0 + xx - 1;
    float v = 0.f;
    if (gy >= 0 && gy < 512 && gx >= 0 && gx < 512)
      v = x[((size_t)(b * 3 + c) << 18) + (gy << 9) + gx];
    xs[c][yy][xx] = v;
  }
  __syncthreads();
  float r[27];
#pragma unroll
  for (int c = 0; c < 3; c++)
#pragma unroll
    for (int ky = 0; ky < 3; ky++)
#pragma unroll
      for (int kx = 0; kx < 3; kx++)
        r[c * 9 + ky * 3 + kx] = xs[c][ty + ky][tx + kx];
  float* outp = g_unary + ((size_t)b * 21 << 18) + ((y0 + ty) << 9) + (x0 + tx);
#pragma unroll
  for (int o = 0; o < 21; o++) {
    float acc = bs[o];
#pragma unroll
    for (int i = 0; i < 27; i++) acc = fmaf(r[i], ws[o * 27 + i], acc);
    outp[(size_t)o << 18] = acc;
  }
}

// ---------------- 4x4 avg-pool of x, folded /13 ----------------
__global__ void k_poolrgb(const float* __restrict__ x) {
  int idx = blockIdx.x * 256 + threadIdx.x;  // over 2*3*128*128
  if (idx >= 98304) return;
  int xp = idx & 127, yp = (idx >> 7) & 127, c = idx >> 14;  // c = b*3+ch
  const float* p = x + ((size_t)c << 18) + ((yp * 4) << 9) + (xp * 4);
  float s = 0.f;
#pragma unroll
  for (int i = 0; i < 4; i++)
#pragma unroll
    for (int j = 0; j < 4; j++) s += p[(i << 9) + j];
  g_rgbp[idx] = s * (1.0f / 208.0f);  // /16 pool, /13 feature scale
}

// ---------------- combined pairwise kernel: w1*bilateral + w2*spatial ----------------
__global__ void k_kernels(const float* __restrict__ pw) {
  __shared__ float rs[3][18][42];
  __shared__ float sA[121], sS[121];
  const int b  = blockIdx.z;
  const int x0 = blockIdx.x * 32, y0 = blockIdx.y * 8;
  const int tx = threadIdx.x, ty = threadIdx.y;
  const int tid = ty * 32 + tx;
  if (tid < 121) {
    int dy = tid / 11 - 5, dx = tid % 11 - 5;
    float d2 = (float)(dy * dy + dx * dx);
    sA[tid] = __expf(-d2 * (1.0f / 800.0f));  // pooled YX/80: (4d/80)^2/2
    sS[tid] = __expf(-d2 * (8.0f / 9.0f));    // pooled YX/3 : (4d/3)^2/2
  }
  for (int i = tid; i < 3 * 18 * 42; i += 256) {
    int c = i / 756, rem = i % 756, yy = rem / 42, xx = rem % 42;
    int gy = y0 + yy - 5, gx = x0 + xx - 5;
    float v = 0.f;
    if (gy >= 0 && gy < 128 && gx >= 0 && gx < 128)
      v = g_rgbp[((b * 3 + c) << 14) + (gy << 7) + gx];
    rs[c][yy][xx] = v;
  }
  __syncthreads();
  const float w1 = pw[0], w2 = pw[1];
  const float r0 = rs[0][ty + 5][tx + 5];
  const float r1 = rs[1][ty + 5][tx + 5];
  const float r2 = rs[2][ty + 5][tx + 5];
  const int y = y0 + ty, xg = x0 + tx;
  float* outp = g_kcomb + ((size_t)b * 121 << 14) + (y << 7) + xg;
  for (int dy = 0; dy < 11; dy++) {
    for (int dx = 0; dx < 11; dx++) {
      int j = dy * 11 + dx;
      int ny = y + dy - 5, nx = xg + dx - 5;
      float val = 0.f;  // OOB entries multiply zero-padded Q patches -> store 0
      if (ny >= 0 && ny < 128 && nx >= 0 && nx < 128) {
        float a = rs[0][ty + dy][tx + dx] - r0;
        float bb = rs[1][ty + dy][tx + dx] - r1;
        float cc = rs[2][ty + dy][tx + dx] - r2;
        float d2 = a * a + bb * bb + cc * cc;
        val = fmaf(w1 * sA[j], __expf(-0.5f * d2), w2 * sS[j]);
      }
      outp[(size_t)j << 14] = val;
    }
  }
}

// ---------------- fused: (uw*unary + upsample(msg)) -> softmax -> 4x4 pool ----------------
// 1 pixel/thread, block 32x8 pixels, pool via shfl(x) + smem(y). grid (16,64,2)
template <bool HAS_MSG>
__global__ void k_softpool(const float* __restrict__ uwp) {
  __shared__ float ms[21][4][10];
  __shared__ float ps[8][8][21];
  const int b  = blockIdx.z;
  const int x0 = blockIdx.x * 32, y0 = blockIdx.y * 8;
  const int tx = threadIdx.x, ty = threadIdx.y;
  const int tid = ty * 32 + tx;
  const float uw = uwp[0];
  if (HAS_MSG) {
    int qx0 = (x0 >> 2) - 1, qy0 = (y0 >> 2) - 1;
    for (int i = tid; i < 21 * 4 * 10; i += 256) {
      int c = i / 40, rem = i % 40, yy = rem / 10, xx = rem % 10;
      int gy = min(max(qy0 + yy, 0), 127), gx = min(max(qx0 + xx, 0), 127);
      ms[c][yy][xx] = g_msg[((b * 21 + c) << 14) + (gy << 7) + gx];
    }
    __syncthreads();
  }
  const int pxp = tx & 3;
  const int ix0 = (tx >> 2) + (pxp >= 2 ? 1 : 0);
  const float wx0 = (pxp == 0) ? 0.375f : (pxp == 1) ? 0.125f : (pxp == 2) ? 0.875f : 0.625f;
  const float wx1 = 1.f - wx0;
  const int pyp = ty & 3;
  const int iy0 = (ty >> 2) + (pyp >= 2 ? 1 : 0);
  const float wy0 = (pyp == 0) ? 0.375f : (pyp == 1) ? 0.125f : (pyp == 2) ? 0.875f : 0.625f;
  const float wy1 = 1.f - wy0;
  const int y = y0 + ty, xg = x0 + tx;
  const float* up = g_unary + ((size_t)b * 21 << 18) + (y << 9) + xg;
  float logit[21];
  float mx = -1e30f;
#pragma unroll
  for (int c = 0; c < 21; c++) {
    float v = uw * up[(size_t)c << 18];
    if (HAS_MSG) {
      float a  = wx0 * ms[c][iy0][ix0]     + wx1 * ms[c][iy0][ix0 + 1];
      float bb = wx0 * ms[c][iy0 + 1][ix0] + wx1 * ms[c][iy0 + 1][ix0 + 1];
      v += wy0 * a + wy1 * bb;
    }
    logit[c] = v;
    mx = fmaxf(mx, v);
  }
  float s = 0.f;
#pragma unroll
  for (int c = 0; c < 21; c++) { float e = __expf(logit[c] - mx); logit[c] = e; s += e; }
  float inv = __frcp_rn(s);
#pragma unroll
  for (int c = 0; c < 21; c++) {
    float q = logit[c] * inv;
    q += __shfl_down_sync(0xffffffffu, q, 1);
    q += __shfl_down_sync(0xffffffffu, q, 2);
    logit[c] = q;
  }
  if ((tx & 3) == 0) {
#pragma unroll
    for (int c = 0; c < 21; c++) ps[ty][tx >> 2][c] = logit[c];
  }
  __syncthreads();
  for (int i = tid; i < 336; i += 256) {
    int c = i % 21, pxx = (i / 21) & 7, pyy = i / 168;
    float sum = ps[pyy * 4 + 0][pxx][c] + ps[pyy * 4 + 1][pxx][c] +
                ps[pyy * 4 + 2][pxx][c] + ps[pyy * 4 + 3][pxx][c];
    int yp = (y0 >> 2) + pyy, xp = (x0 >> 2) + pxx;
    g_qb[((b * 21 + c) << 14) + (yp << 7) + xp] = sum * 0.0625f;
  }
}

// ---------------- pixel-adaptive 11x11 message at 128x128 ----------------
// 32-wide tile (conflict-free LDS), 2 output rows/thread (q reuse), channels
// split in 2 groups across blockIdx.z. block 32x4=128 thr, grid (4,16,4).
__global__ void k_pac() {
  __shared__ float qs[11][18][42];
  const int bz = blockIdx.z;
  const int b  = bz >> 1;
  const int c0 = (bz & 1) * 11;
  const int NCv = (bz & 1) ? 10 : 11;
  const int x0 = blockIdx.x * 32, y0 = blockIdx.y * 8;
  const int tx = threadIdx.x, ty = threadIdx.y;
  const int tid = ty * 32 + tx;
  for (int i = tid; i < 11 * 18 * 42; i += 128) {
    int c = i / 756, rem = i % 756, yy = rem / 42, xx = rem % 42;
    int gy = y0 + yy - 5, gx = x0 + xx - 5;
    float v = 0.f;
    if (c0 + c < 21 && gy >= 0 && gy < 128 && gx >= 0 && gx < 128)
      v = g_qb[((b * 21 + c0 + c) << 14) + (gy << 7) + gx];
    qs[c][yy][xx] = v;
  }
  __syncthreads();
  float a0[11], a1[11];
#pragma unroll
  for (int c = 0; c < 11; c++) { a0[c] = 0.f; a1[c] = 0.f; }
  const int row0 = y0 + ty * 2;   // thread computes rows row0, row0+1
  const int ly0 = ty * 2;         // smem row offset (smem row 0 = y0-5)
  const float* kp0 = g_kcomb + ((size_t)b * 121 << 14) + (row0 << 7) + x0 + tx;
  const float* kp1 = kp0 + 128;
  for (int rr = 0; rr < 12; rr++) {       // q row = row0 - 5 + rr
    for (int dx = 0; dx < 11; dx++) {
      float kv0 = (rr < 11) ? __ldg(kp0 + ((size_t)(rr * 11 + dx) << 14)) : 0.f;
      float kv1 = (rr >= 1) ? __ldg(kp1 + ((size_t)((rr - 1) * 11 + dx) << 14)) : 0.f;
      const float* q = &qs[0][ly0 + rr][tx + dx];
#pragma unroll
      for (int c = 0; c < 11; c++) {
        float qv = q[c * 756];
        a0[c] = fmaf(kv0, qv, a0[c]);
        a1[c] = fmaf(kv1, qv, a1[c]);
      }
    }
  }
  float* mp = g_msg + ((size_t)(b * 21 + c0) << 14) + (row0 << 7) + x0 + tx;
  for (int c = 0; c < NCv; c++) {
    mp[(size_t)c << 14]         = a0[c];
    mp[((size_t)c << 14) + 128] = a1[c];
  }
}

// ---------------- last step: logQ = uw*unary + upsample(msg) -> d_out ----------------
__global__ void k_final(const float* __restrict__ uwp, float* __restrict__ out) {
  __shared__ float ms[21][4][10];
  const int b  = blockIdx.z;
  const int x0 = blockIdx.x * 32, y0 = blockIdx.y * 8;
  const int tx = threadIdx.x, ty = threadIdx.y;
  const int tid = ty * 32 + tx;
  const float uw = uwp[0];
  {
    int qx0 = (x0 >> 2) - 1, qy0 = (y0 >> 2) - 1;
    for (int i = tid; i < 21 * 4 * 10; i += 256) {
      int c = i / 40, rem = i % 40, yy = rem / 10, xx = rem % 10;
      int gy = min(max(qy0 + yy, 0), 127), gx = min(max(qx0 + xx, 0), 127);
      ms[c][yy][xx] = g_msg[((b * 21 + c) << 14) + (gy << 7) + gx];
    }
    __syncthreads();
  }
  const int pxp = tx & 3;
  const int ix0 = (tx >> 2) + (pxp >= 2 ? 1 : 0);
  const float wx0 = (pxp == 0) ? 0.375f : (pxp == 1) ? 0.125f : (pxp == 2) ? 0.875f : 0.625f;
  const float wx1 = 1.f - wx0;
  const int pyp = ty & 3;
  const int iy0 = (ty >> 2) + (pyp >= 2 ? 1 : 0);
  const float wy0 = (pyp == 0) ? 0.375f : (pyp == 1) ? 0.125f : (pyp == 2) ? 0.875f : 0.625f;
  const float wy1 = 1.f - wy0;
  const int y = y0 + ty, xg = x0 + tx;
  const float* up = g_unary + ((size_t)b * 21 << 18) + (y << 9) + xg;
  float* op = out + ((size_t)b * 21 << 18) + (y << 9) + xg;
#pragma unroll
  for (int c = 0; c < 21; c++) {
    float v = uw * up[(size_t)c << 18];
    float a  = wx0 * ms[c][iy0][ix0]     + wx1 * ms[c][iy0][ix0 + 1];
    float bb = wx0 * ms[c][iy0 + 1][ix0] + wx1 * ms[c][iy0 + 1][ix0 + 1];
    op[(size_t)c << 18] = v + wy0 * a + wy1 * bb;
  }
}

extern "C" void kernel_launch(void* const* d_in, const int* in_sizes, int n_in,
                              void* d_out, int out_size) {
  const float* x    = (const float*)d_in[0];
  const float* w    = (const float*)d_in[1];
  const float* bias = (const float*)d_in[2];
  const float* uw   = (const float*)d_in[3];
  const float* pw   = (const float*)d_in[4];
  float* out = (float*)d_out;
  (void)in_sizes; (void)n_in; (void)out_size;

  dim3 b32x8(32, 8);
  k_conv<<<dim3(16, 64, 2), b32x8>>>(x, w, bias);
  k_poolrgb<<<384, 256>>>(x);
  k_kernels<<<dim3(4, 16, 2), b32x8>>>(pw);
  k_softpool<false><<<dim3(16, 64, 2), b32x8>>>(uw);
  for (int t = 0; t < 5; t++) {
    k_pac<<<dim3(4, 16, 4), dim3(32, 4)>>>();
    if (t < 4) k_softpool<true><<<dim3(16, 64, 2), b32x8>>>(uw);
    else       k_final<<<dim3(16, 64, 2), b32x8>>>(uw, out);
  }
}

// round 4
// speedup vs baseline: 1.2335x; 1.2335x over previous
#include <cuda_runtime.h>

// ---------------- problem constants ----------------
// B=2, C=21, H=W=512, pooled 128x128, K=11 (radius 5), 5 steps, pad=(0,0)

// ---------------- scratch (device globals; no mallocs allowed) ----------------
__device__ float g_unary[11010048];   // [2][21][512][512]
__device__ float g_qb[688128];        // [2][21][128][128]
__device__ float g_msgp[2752512];     // [4 tap-groups][2][21][128][128] partial messages
__device__ float g_kcomb[3964928];    // [2][121][128][128]  (j-major)
__device__ float g_rgbp[98304];       // [2][3][128][128]    (already /13)

// ---------------- backbone 3x3 conv, 3 -> 21 ----------------
__global__ void k_conv(const float* __restrict__ x, const float* __restrict__ w,
                       const float* __restrict__ bias) {
  __shared__ float xs[3][10][34];
  __shared__ float ws[567];
  __shared__ float bs[21];
  const int b  = blockIdx.z;
  const int x0 = blockIdx.x * 32, y0 = blockIdx.y * 8;
  const int tx = threadIdx.x, ty = threadIdx.y;
  const int tid = ty * 32 + tx;
  for (int i = tid; i < 567; i += 256) ws[i] = w[i];
  if (tid < 21) bs[tid] = bias[tid];
  for (int i = tid; i < 3 * 10 * 34; i += 256) {
    int c = i / 340, rem = i % 340, yy = rem / 34, xx = rem % 34;
    int gy = y0 + yy - 1, gx = x0 + xx - 1;
    float v = 0.f;
    if (gy >= 0 && gy < 512 && gx >= 0 && gx < 512)
      v = x[((size_t)(b * 3 + c) << 18) + (gy << 9) + gx];
    xs[c][yy][xx] = v;
  }
  __syncthreads();
  float r[27];
#pragma unroll
  for (int c = 0; c < 3; c++)
#pragma unroll
    for (int ky = 0; ky < 3; ky++)
#pragma unroll
      for (int kx = 0; kx < 3; kx++)
        r[c * 9 + ky * 3 + kx] = xs[c][ty + ky][tx + kx];
  float* outp = g_unary + ((size_t)b * 21 << 18) + ((y0 + ty) << 9) + (x0 + tx);
#pragma unroll
  for (int o = 0; o < 21; o++) {
    float acc = bs[o];
#pragma unroll
    for (int i = 0; i < 27; i++) acc = fmaf(r[i], ws[o * 27 + i], acc);
    outp[(size_t)o << 18] = acc;
  }
}

// ---------------- 4x4 avg-pool of x, folded /13 ----------------
__global__ void k_poolrgb(const float* __restrict__ x) {
  int idx = blockIdx.x * 256 + threadIdx.x;  // over 2*3*128*128
  if (idx >= 98304) return;
  int xp = idx & 127, yp = (idx >> 7) & 127, c = idx >> 14;  // c = b*3+ch
  const float* p = x + ((size_t)c << 18) + ((yp * 4) << 9) + (xp * 4);
  float s = 0.f;
#pragma unroll
  for (int i = 0; i < 4; i++)
#pragma unroll
    for (int j = 0; j < 4; j++) s += p[(i << 9) + j];
  g_rgbp[idx] = s * (1.0f / 208.0f);  // /16 pool, /13 feature scale
}

// ---------------- combined pairwise kernel: w1*bilateral + w2*spatial ----------------
__global__ void k_kernels(const float* __restrict__ pw) {
  __shared__ float rs[3][18][42];
  __shared__ float sA[121], sS[121];
  const int b  = blockIdx.z;
  const int x0 = blockIdx.x * 32, y0 = blockIdx.y * 8;
  const int tx = threadIdx.x, ty = threadIdx.y;
  const int tid = ty * 32 + tx;
  if (tid < 121) {
    int dy = tid / 11 - 5, dx = tid % 11 - 5;
    float d2 = (float)(dy * dy + dx * dx);
    sA[tid] = __expf(-d2 * (1.0f / 800.0f));  // pooled YX/80: (4d/80)^2/2
    sS[tid] = __expf(-d2 * (8.0f / 9.0f));    // pooled YX/3 : (4d/3)^2/2
  }
  for (int i = tid; i < 3 * 18 * 42; i += 256) {
    int c = i / 756, rem = i % 756, yy = rem / 42, xx = rem % 42;
    int gy = y0 + yy - 5, gx = x0 + xx - 5;
    float v = 0.f;
    if (gy >= 0 && gy < 128 && gx >= 0 && gx < 128)
      v = g_rgbp[((b * 3 + c) << 14) + (gy << 7) + gx];
    rs[c][yy][xx] = v;
  }
  __syncthreads();
  const float w1 = pw[0], w2 = pw[1];
  const float r0 = rs[0][ty + 5][tx + 5];
  const float r1 = rs[1][ty + 5][tx + 5];
  const float r2 = rs[2][ty + 5][tx + 5];
  const int y = y0 + ty, xg = x0 + tx;
  float* outp = g_kcomb + ((size_t)b * 121 << 14) + (y << 7) + xg;
  for (int dy = 0; dy < 11; dy++) {
    for (int dx = 0; dx < 11; dx++) {
      int j = dy * 11 + dx;
      int ny = y + dy - 5, nx = xg + dx - 5;
      float val = 0.f;  // OOB entries multiply zero-padded Q patches -> store 0
      if (ny >= 0 && ny < 128 && nx >= 0 && nx < 128) {
        float a = rs[0][ty + dy][tx + dx] - r0;
        float bb = rs[1][ty + dy][tx + dx] - r1;
        float cc = rs[2][ty + dy][tx + dx] - r2;
        float d2 = a * a + bb * bb + cc * cc;
        val = fmaf(w1 * sA[j], __expf(-0.5f * d2), w2 * sS[j]);
      }
      outp[(size_t)j << 14] = val;
    }
  }
}

// ---------------- fused: (uw*unary + upsample(msg)) -> softmax -> 4x4 pool ----------------
// 1 pixel/thread, block 32x8 pixels, pool via shfl(x) + smem(y). grid (16,64,2)
template <bool HAS_MSG>
__global__ void k_softpool(const float* __restrict__ uwp) {
  __shared__ float ms[21][4][10];
  __shared__ float ps[8][8][21];
  const int b  = blockIdx.z;
  const int x0 = blockIdx.x * 32, y0 = blockIdx.y * 8;
  const int tx = threadIdx.x, ty = threadIdx.y;
  const int tid = ty * 32 + tx;
  const float uw = uwp[0];
  if (HAS_MSG) {
    int qx0 = (x0 >> 2) - 1, qy0 = (y0 >> 2) - 1;
    for (int i = tid; i < 21 * 4 * 10; i += 256) {
      int c = i / 40, rem = i % 40, yy = rem / 10, xx = rem % 10;
      int gy = min(max(qy0 + yy, 0), 127), gx = min(max(qx0 + xx, 0), 127);
      size_t idx = (size_t)((b * 21 + c) << 14) + (gy << 7) + gx;
      ms[c][yy][xx] = g_msgp[idx] + g_msgp[688128 + idx] +
                      g_msgp[2 * 688128 + idx] + g_msgp[3 * 688128 + idx];
    }
    __syncthreads();
  }
  const int pxp = tx & 3;
  const int ix0 = (tx >> 2) + (pxp >= 2 ? 1 : 0);
  const float wx0 = (pxp == 0) ? 0.375f : (pxp == 1) ? 0.125f : (pxp == 2) ? 0.875f : 0.625f;
  const float wx1 = 1.f - wx0;
  const int pyp = ty & 3;
  const int iy0 = (ty >> 2) + (pyp >= 2 ? 1 : 0);
  const float wy0 = (pyp == 0) ? 0.375f : (pyp == 1) ? 0.125f : (pyp == 2) ? 0.875f : 0.625f;
  const float wy1 = 1.f - wy0;
  const int y = y0 + ty, xg = x0 + tx;
  const float* up = g_unary + ((size_t)b * 21 << 18) + (y << 9) + xg;
  float logit[21];
  float mx = -1e30f;
#pragma unroll
  for (int c = 0; c < 21; c++) {
    float v = uw * up[(size_t)c << 18];
    if (HAS_MSG) {
      float a  = wx0 * ms[c][iy0][ix0]     + wx1 * ms[c][iy0][ix0 + 1];
      float bb = wx0 * ms[c][iy0 + 1][ix0] + wx1 * ms[c][iy0 + 1][ix0 + 1];
      v += wy0 * a + wy1 * bb;
    }
    logit[c] = v;
    mx = fmaxf(mx, v);
  }
  float s = 0.f;
#pragma unroll
  for (int c = 0; c < 21; c++) { float e = __expf(logit[c] - mx); logit[c] = e; s += e; }
  float inv = __frcp_rn(s);
#pragma unroll
  for (int c = 0; c < 21; c++) {
    float q = logit[c] * inv;
    q += __shfl_down_sync(0xffffffffu, q, 1);
    q += __shfl_down_sync(0xffffffffu, q, 2);
    logit[c] = q;
  }
  if ((tx & 3) == 0) {
#pragma unroll
    for (int c = 0; c < 21; c++) ps[ty][tx >> 2][c] = logit[c];
  }
  __syncthreads();
  for (int i = tid; i < 336; i += 256) {
    int c = i % 21, pxx = (i / 21) & 7, pyy = i / 168;
    float sum = ps[pyy * 4 + 0][pxx][c] + ps[pyy * 4 + 1][pxx][c] +
                ps[pyy * 4 + 2][pxx][c] + ps[pyy * 4 + 3][pxx][c];
    int yp = (y0 >> 2) + pyy, xp = (x0 >> 2) + pxx;
    g_qb[((b * 21 + c) << 14) + (yp << 7) + xp] = sum * 0.0625f;
  }
}

// ---------------- pixel-adaptive 11x11 message at 128x128 ----------------
// Tap-split x4: block z = b*4+g; group g handles kernel rows dy in [3g, 3g+3)
// (g=3: rows 9,10), writing partial sums to g_msgp[g]. 2 output rows/thread
// (q reuse across the two k streams). block 32x4=128 thr covering 32x8 pixels,
// grid (4,16,8) = 512 blocks -> ~14 warps/SM.
__global__ __launch_bounds__(128, 5) void k_pac() {
  __shared__ float qs[21][10][42];
  const int bz = blockIdx.z;
  const int b  = bz >> 2, g = bz & 3;
  const int s  = g * 3;
  const int e  = (g == 3) ? 11 : s + 3;   // a0 covers k rows [s,e); a1 same via rr-1
  const int x0 = blockIdx.x * 32, y0 = blockIdx.y * 8;
  const int tx = threadIdx.x, ty = threadIdx.y;
  const int tid = ty * 32 + tx;
  const int qy0 = y0 - 5 + s;
  for (int i = tid; i < 21 * 10 * 42; i += 128) {
    int c = i / 420, rem = i % 420, yy = rem / 42, xx = rem % 42;
    int gy = qy0 + yy, gx = x0 - 5 + xx;
    float v = 0.f;
    if (gy >= 0 && gy < 128 && gx >= 0 && gx < 128)
      v = g_qb[((b * 21 + c) << 14) + (gy << 7) + gx];
    qs[c][yy][xx] = v;
  }
  __syncthreads();
  float a0[21], a1[21];
#pragma unroll
  for (int c = 0; c < 21; c++) { a0[c] = 0.f; a1[c] = 0.f; }
  const int row0 = y0 + ty * 2;
  const float* kp0 = g_kcomb + ((size_t)b * 121 << 14) + (row0 << 7) + x0 + tx;
  const float* kp1 = kp0 + 128;
  for (int rr = s; rr <= e; rr++) {     // q row = row0 - 5 + rr
    const float* qrow = &qs[0][ty * 2 + rr - s][tx];
    const bool h0 = (rr < e), h1 = (rr > s);
#pragma unroll
    for (int dx = 0; dx < 11; dx++) {
      float kv0 = h0 ? __ldg(kp0 + ((size_t)(rr * 11 + dx) << 14)) : 0.f;
      float kv1 = h1 ? __ldg(kp1 + ((size_t)((rr - 1) * 11 + dx) << 14)) : 0.f;
#pragma unroll
      for (int c = 0; c < 21; c++) {
        float qv = qrow[c * 420 + dx];
        a0[c] = fmaf(kv0, qv, a0[c]);
        a1[c] = fmaf(kv1, qv, a1[c]);
      }
    }
  }
  float* mp = g_msgp + (size_t)g * 688128 + ((size_t)b * 21 << 14) + (row0 << 7) + x0 + tx;
#pragma unroll
  for (int c = 0; c < 21; c++) {
    mp[(size_t)c << 14]         = a0[c];
    mp[((size_t)c << 14) + 128] = a1[c];
  }
}

// ---------------- last step: logQ = uw*unary + upsample(msg) -> d_out ----------------
__global__ void k_final(const float* __restrict__ uwp, float* __restrict__ out) {
  __shared__ float ms[21][4][10];
  const int b  = blockIdx.z;
  const int x0 = blockIdx.x * 32, y0 = blockIdx.y * 8;
  const int tx = threadIdx.x, ty = threadIdx.y;
  const int tid = ty * 32 + tx;
  const float uw = uwp[0];
  {
    int qx0 = (x0 >> 2) - 1, qy0 = (y0 >> 2) - 1;
    for (int i = tid; i < 21 * 4 * 10; i += 256) {
      int c = i / 40, rem = i % 40, yy = rem / 10, xx = rem % 10;
      int gy = min(max(qy0 + yy, 0), 127), gx = min(max(qx0 + xx, 0), 127);
      size_t idx = (size_t)((b * 21 + c) << 14) + (gy << 7) + gx;
      ms[c][yy][xx] = g_msgp[idx] + g_msgp[688128 + idx] +
                      g_msgp[2 * 688128 + idx] + g_msgp[3 * 688128 + idx];
    }
    __syncthreads();
  }
  const int pxp = tx & 3;
  const int ix0 = (tx >> 2) + (pxp >= 2 ? 1 : 0);
  const float wx0 = (pxp == 0) ? 0.375f : (pxp == 1) ? 0.125f : (pxp == 2) ? 0.875f : 0.625f;
  const float wx1 = 1.f - wx0;
  const int pyp = ty & 3;
  const int iy0 = (ty >> 2) + (pyp >= 2 ? 1 : 0);
  const float wy0 = (pyp == 0) ? 0.375f : (pyp == 1) ? 0.125f : (pyp == 2) ? 0.875f : 0.625f;
  const float wy1 = 1.f - wy0;
  const int y = y0 + ty, xg = x0 + tx;
  const float* up = g_unary + ((size_t)b * 21 << 18) + (y << 9) + xg;
  float* op = out + ((size_t)b * 21 << 18) + (y << 9) + xg;
#pragma unroll
  for (int c = 0; c < 21; c++) {
    float v = uw * up[(size_t)c << 18];
    float a  = wx0 * ms[c][iy0][ix0]     + wx1 * ms[c][iy0][ix0 + 1];
    float bb = wx0 * ms[c][iy0 + 1][ix0] + wx1 * ms[c][iy0 + 1][ix0 + 1];
    op[(size_t)c << 18] = v + wy0 * a + wy1 * bb;
  }
}

extern "C" void kernel_launch(void* const* d_in, const int* in_sizes, int n_in,
                              void* d_out, int out_size) {
  const float* x    = (const float*)d_in[0];
  const float* w    = (const float*)d_in[1];
  const float* bias = (const float*)d_in[2];
  const float* uw   = (const float*)d_in[3];
  const float* pw   = (const float*)d_in[4];
  float* out = (float*)d_out;
  (void)in_sizes; (void)n_in; (void)out_size;

  dim3 b32x8(32, 8);
  k_conv<<<dim3(16, 64, 2), b32x8>>>(x, w, bias);
  k_poolrgb<<<384, 256>>>(x);
  k_kernels<<<dim3(4, 16, 2), b32x8>>>(pw);
  k_softpool<false><<<dim3(16, 64, 2), b32x8>>>(uw);
  for (int t = 0; t < 5; t++) {
    k_pac<<<dim3(4, 16, 8), dim3(32, 4)>>>();
    if (t < 4) k_softpool<true><<<dim3(16, 64, 2), b32x8>>>(uw);
    else       k_final<<<dim3(16, 64, 2), b32x8>>>(uw, out);
  }
}

// round 6
// speedup vs baseline: 1.3654x; 1.1070x over previous
#include <cuda_runtime.h>

// ---------------- problem constants ----------------
// B=2, C=21, H=W=512, pooled 128x128, K=11 (radius 5), 5 steps, pad=(0,0)

// ---------------- scratch (device globals; no mallocs allowed) ----------------
__device__ float g_unary[11010048];   // [2][21][512][512]
__device__ float g_qb[688128];        // [2][21][128][128]
__device__ float g_msgp[2752512];     // [4 tap-groups][2][21][128][128] partial messages
__device__ float g_kcomb[3964928];    // [2][121][128][128]  (j-major)
__device__ float g_rgbp[98304];       // [2][3][128][128]    (already /13)

// ---------------- backbone 3x3 conv, 3 -> 21 ----------------
__global__ void k_conv(const float* __restrict__ x, const float* __restrict__ w,
                       const float* __restrict__ bias) {
  __shared__ float xs[3][10][34];
  __shared__ float ws[567];
  __shared__ float bs[21];
  const int b  = blockIdx.z;
  const int x0 = blockIdx.x * 32, y0 = blockIdx.y * 8;
  const int tx = threadIdx.x, ty = threadIdx.y;
  const int tid = ty * 32 + tx;
  for (int i = tid; i < 567; i += 256) ws[i] = w[i];
  if (tid < 21) bs[tid] = bias[tid];
  for (int i = tid; i < 3 * 10 * 34; i += 256) {
    int c = i / 340, rem = i % 340, yy = rem / 34, xx = rem % 34;
    int gy = y0 + yy - 1, gx = x0 + xx - 1;
    float v = 0.f;
    if (gy >= 0 && gy < 512 && gx >= 0 && gx < 512)
      v = x[((size_t)(b * 3 + c) << 18) + (gy << 9) + gx];
    xs[c][yy][xx] = v;
  }
  __syncthreads();
  float r[27];
#pragma unroll
  for (int c = 0; c < 3; c++)
#pragma unroll
    for (int ky = 0; ky < 3; ky++)
#pragma unroll
      for (int kx = 0; kx < 3; kx++)
        r[c * 9 + ky * 3 + kx] = xs[c][ty + ky][tx + kx];
  float* outp = g_unary + ((size_t)b * 21 << 18) + ((y0 + ty) << 9) + (x0 + tx);
#pragma unroll
  for (int o = 0; o < 21; o++) {
    float acc = bs[o];
#pragma unroll
    for (int i = 0; i < 27; i++) acc = fmaf(r[i], ws[o * 27 + i], acc);
    outp[(size_t)o << 18] = acc;
  }
}

// ---------------- 4x4 avg-pool of x, folded /13 ----------------
__global__ void k_poolrgb(const float* __restrict__ x) {
  int idx = blockIdx.x * 256 + threadIdx.x;  // over 2*3*128*128
  if (idx >= 98304) return;
  int xp = idx & 127, yp = (idx >> 7) & 127, c = idx >> 14;  // c = b*3+ch
  const float* p = x + ((size_t)c << 18) + ((yp * 4) << 9) + (xp * 4);
  float s = 0.f;
#pragma unroll
  for (int i = 0; i < 4; i++)
#pragma unroll
    for (int j = 0; j < 4; j++) s += p[(i << 9) + j];
  g_rgbp[idx] = s * (1.0f / 208.0f);  // /16 pool, /13 feature scale
}

// ---------------- combined pairwise kernel: w1*bilateral + w2*spatial ----------------
__global__ void k_kernels(const float* __restrict__ pw) {
  __shared__ float rs[3][18][42];
  __shared__ float sA[121], sS[121];
  const int b  = blockIdx.z;
  const int x0 = blockIdx.x * 32, y0 = blockIdx.y * 8;
  const int tx = threadIdx.x, ty = threadIdx.y;
  const int tid = ty * 32 + tx;
  if (tid < 121) {
    int dy = tid / 11 - 5, dx = tid % 11 - 5;
    float d2 = (float)(dy * dy + dx * dx);
    sA[tid] = __expf(-d2 * (1.0f / 800.0f));  // pooled YX/80: (4d/80)^2/2
    sS[tid] = __expf(-d2 * (8.0f / 9.0f));    // pooled YX/3 : (4d/3)^2/2
  }
  for (int i = tid; i < 3 * 18 * 42; i += 256) {
    int c = i / 756, rem = i % 756, yy = rem / 42, xx = rem % 42;
    int gy = y0 + yy - 5, gx = x0 + xx - 5;
    float v = 0.f;
    if (gy >= 0 && gy < 128 && gx >= 0 && gx < 128)
      v = g_rgbp[((b * 3 + c) << 14) + (gy << 7) + gx];
    rs[c][yy][xx] = v;
  }
  __syncthreads();
  const float w1 = pw[0], w2 = pw[1];
  const float r0 = rs[0][ty + 5][tx + 5];
  const float r1 = rs[1][ty + 5][tx + 5];
  const float r2 = rs[2][ty + 5][tx + 5];
  const int y = y0 + ty, xg = x0 + tx;
  float* outp = g_kcomb + ((size_t)b * 121 << 14) + (y << 7) + xg;
  for (int dy = 0; dy < 11; dy++) {
    for (int dx = 0; dx < 11; dx++) {
      int j = dy * 11 + dx;
      int ny = y + dy - 5, nx = xg + dx - 5;
      float val = 0.f;  // OOB entries multiply zero-padded Q patches -> store 0
      if (ny >= 0 && ny < 128 && nx >= 0 && nx < 128) {
        float a = rs[0][ty + dy][tx + dx] - r0;
        float bb = rs[1][ty + dy][tx + dx] - r1;
        float cc = rs[2][ty + dy][tx + dx] - r2;
        float d2 = a * a + bb * bb + cc * cc;
        val = fmaf(w1 * sA[j], __expf(-0.5f * d2), w2 * sS[j]);
      }
      outp[(size_t)j << 14] = val;
    }
  }
}

// ---------------- fused: (uw*unary + upsample(msg)) -> softmax -> 4x4 pool ----------------
// 1 pixel/thread, block 32x8 pixels, pool via shfl(x) + smem(y). grid (16,64,2)
template <bool HAS_MSG>
__global__ void k_softpool(const float* __restrict__ uwp) {
  __shared__ float ms[21][4][10];
  __shared__ float ps[8][8][21];
  const int b  = blockIdx.z;
  const int x0 = blockIdx.x * 32, y0 = blockIdx.y * 8;
  const int tx = threadIdx.x, ty = threadIdx.y;
  const int tid = ty * 32 + tx;
  const float uw = uwp[0];
  if (HAS_MSG) {
    int qx0 = (x0 >> 2) - 1, qy0 = (y0 >> 2) - 1;
    for (int i = tid; i < 21 * 4 * 10; i += 256) {
      int c = i / 40, rem = i % 40, yy = rem / 10, xx = rem % 10;
      int gy = min(max(qy0 + yy, 0), 127), gx = min(max(qx0 + xx, 0), 127);
      size_t idx = (size_t)((b * 21 + c) << 14) + (gy << 7) + gx;
      ms[c][yy][xx] = g_msgp[idx] + g_msgp[688128 + idx] +
                      g_msgp[2 * 688128 + idx] + g_msgp[3 * 688128 + idx];
    }
    __syncthreads();
  }
  const int pxp = tx & 3;
  const int ix0 = (tx >> 2) + (pxp >= 2 ? 1 : 0);
  const float wx0 = (pxp == 0) ? 0.375f : (pxp == 1) ? 0.125f : (pxp == 2) ? 0.875f : 0.625f;
  const float wx1 = 1.f - wx0;
  const int pyp = ty & 3;
  const int iy0 = (ty >> 2) + (pyp >= 2 ? 1 : 0);
  const float wy0 = (pyp == 0) ? 0.375f : (pyp == 1) ? 0.125f : (pyp == 2) ? 0.875f : 0.625f;
  const float wy1 = 1.f - wy0;
  const int y = y0 + ty, xg = x0 + tx;
  const float* up = g_unary + ((size_t)b * 21 << 18) + (y << 9) + xg;
  float logit[21];
  float mx = -1e30f;
#pragma unroll
  for (int c = 0; c < 21; c++) {
    float v = uw * up[(size_t)c << 18];
    if (HAS_MSG) {
      float a  = wx0 * ms[c][iy0][ix0]     + wx1 * ms[c][iy0][ix0 + 1];
      float bb = wx0 * ms[c][iy0 + 1][ix0] + wx1 * ms[c][iy0 + 1][ix0 + 1];
      v += wy0 * a + wy1 * bb;
    }
    logit[c] = v;
    mx = fmaxf(mx, v);
  }
  float s = 0.f;
#pragma unroll
  for (int c = 0; c < 21; c++) { float e = __expf(logit[c] - mx); logit[c] = e; s += e; }
  float inv = __frcp_rn(s);
#pragma unroll
  for (int c = 0; c < 21; c++) {
    float q = logit[c] * inv;
    q += __shfl_down_sync(0xffffffffu, q, 1);
    q += __shfl_down_sync(0xffffffffu, q, 2);
    logit[c] = q;
  }
  if ((tx & 3) == 0) {
#pragma unroll
    for (int c = 0; c < 21; c++) ps[ty][tx >> 2][c] = logit[c];
  }
  __syncthreads();
  for (int i = tid; i < 336; i += 256) {
    int c = i % 21, pxx = (i / 21) & 7, pyy = i / 168;
    float sum = ps[pyy * 4 + 0][pxx][c] + ps[pyy * 4 + 1][pxx][c] +
                ps[pyy * 4 + 2][pxx][c] + ps[pyy * 4 + 3][pxx][c];
    int yp = (y0 >> 2) + pyy, xp = (x0 >> 2) + pxx;
    g_qb[((b * 21 + c) << 14) + (yp << 7) + xp] = sum * 0.0625f;
  }
}

// ---------------- pixel-adaptive 11x11 message at 128x128 ----------------
// x4-vectorized, tap-split x4. Block (32,8): full 128-wide row strip, 4 rows,
// channels split in 2 groups (ty>>2). Each thread: 4 consecutive x pixels of
// one row, 11 channels. kv via LDG.128, q via LDS.128 (4 per (rr,c) feeding
// 44 FMAs). grid (1,32,8): z = b*4 + tap-group (rows [3g,3g+3), g=3: [9,11)).
__global__ __launch_bounds__(256, 2) void k_pac() {
  __shared__ float qs[22][6][144];   // ch 21 = zero pad (keeps loops uniform)
  const int bz = blockIdx.z;
  const int b  = bz >> 2, g = bz & 3;
  const int s  = g * 3;
  const int nrr = (g == 3) ? 2 : 3;
  const int y0 = blockIdx.y * 4;
  const int tx = threadIdx.x;
  const int ty = threadIdx.y & 3;        // output row within strip
  const int tz = threadIdx.y >> 2;       // channel group: 0 -> c 0..10, 1 -> c 11..20(+pad)
  const int tid = threadIdx.y * 32 + tx;
  const int qy0 = y0 - 5 + s;
  for (int i = tid; i < 22 * 6 * 144; i += 256) {
    int c = i / 864, rem = i % 864, r = rem / 144, xx = rem % 144;
    int gy = qy0 + r, gx = xx - 5;
    float v = 0.f;
    if (c < 21 && xx < 138 && gy >= 0 && gy < 128 && gx >= 0 && gx < 128)
      v = g_qb[((b * 21 + c) << 14) + (gy << 7) + gx];
    qs[c][r][xx] = v;
  }
  __syncthreads();
  const int c0 = tz * 11;
  const int y  = y0 + ty;
  const int xb = tx * 4;
  float acc[11][4];
#pragma unroll
  for (int c = 0; c < 11; c++)
#pragma unroll
    for (int o = 0; o < 4; o++) acc[c][o] = 0.f;
  const float* kbase = g_kcomb + ((size_t)b * 121 << 14) + (y << 7) + xb;
  for (int rr = s; rr < s + nrr; rr++) {
    float4 kv[11];
#pragma unroll
    for (int dx = 0; dx < 11; dx++)
      kv[dx] = __ldg(reinterpret_cast<const float4*>(kbase + ((size_t)(rr * 11 + dx) << 14)));
    const int r = ty + rr - s;   // smem row index
#pragma unroll
    for (int c = 0; c < 11; c++) {
      const float4* qp = reinterpret_cast<const float4*>(&qs[c0 + c][r][xb]);
      float4 q0 = qp[0], q1 = qp[1], q2 = qp[2], q3 = qp[3];
      float qf[16] = {q0.x, q0.y, q0.z, q0.w, q1.x, q1.y, q1.z, q1.w,
                      q2.x, q2.y, q2.z, q2.w, q3.x, q3.y, q3.z, q3.w};
#pragma unroll
      for (int dx = 0; dx < 11; dx++) {
        acc[c][0] = fmaf(kv[dx].x, qf[dx + 0], acc[c][0]);
        acc[c][1] = fmaf(kv[dx].y, qf[dx + 1], acc[c][1]);
        acc[c][2] = fmaf(kv[dx].z, qf[dx + 2], acc[c][2]);
        acc[c][3] = fmaf(kv[dx].w, qf[dx + 3], acc[c][3]);
      }
    }
  }
  float* mp = g_msgp + (size_t)g * 688128 + ((size_t)(b * 21 + c0) << 14) + (y << 7) + xb;
#pragma unroll
  for (int c = 0; c < 11; c++) {
    if (c0 + c < 21) {
      float4 v = make_float4(acc[c][0], acc[c][1], acc[c][2], acc[c][3]);
      *reinterpret_cast<float4*>(mp + ((size_t)c << 14)) = v;
    }
  }
}

// ---------------- last step: logQ = uw*unary + upsample(msg) -> d_out ----------------
__global__ void k_final(const float* __restrict__ uwp, float* __restrict__ out) {
  __shared__ float ms[21][4][10];
  const int b  = blockIdx.z;
  const int x0 = blockIdx.x * 32, y0 = blockIdx.y * 8;
  const int tx = threadIdx.x, ty = threadIdx.y;
  const int tid = ty * 32 + tx;
  const float uw = uwp[0];
  {
    int qx0 = (x0 >> 2) - 1, qy0 = (y0 >> 2) - 1;
    for (int i = tid; i < 21 * 4 * 10; i += 256) {
      int c = i / 40, rem = i % 40, yy = rem / 10, xx = rem % 10;
      int gy = min(max(qy0 + yy, 0), 127), gx = min(max(qx0 + xx, 0), 127);
      size_t idx = (size_t)((b * 21 + c) << 14) + (gy << 7) + gx;
      ms[c][yy][xx] = g_msgp[idx] + g_msgp[688128 + idx] +
                      g_msgp[2 * 688128 + idx] + g_msgp[3 * 688128 + idx];
    }
    __syncthreads();
  }
  const int pxp = tx & 3;
  const int ix0 = (tx >> 2) + (pxp >= 2 ? 1 : 0);
  const float wx0 = (pxp == 0) ? 0.375f : (pxp == 1) ? 0.125f : (pxp == 2) ? 0.875f : 0.625f;
  const float wx1 = 1.f - wx0;
  const int pyp = ty & 3;
  const int iy0 = (ty >> 2) + (pyp >= 2 ? 1 : 0);
  const float wy0 = (pyp == 0) ? 0.375f : (pyp == 1) ? 0.125f : (pyp == 2) ? 0.875f : 0.625f;
  const float wy1 = 1.f - wy0;
  const int y = y0 + ty, xg = x0 + tx;
  const float* up = g_unary + ((size_t)b * 21 << 18) + (y << 9) + xg;
  float* op = out + ((size_t)b * 21 << 18) + (y << 9) + xg;
#pragma unroll
  for (int c = 0; c < 21; c++) {
    float v = uw * up[(size_t)c << 18];
    float a  = wx0 * ms[c][iy0][ix0]     + wx1 * ms[c][iy0][ix0 + 1];
    float bb = wx0 * ms[c][iy0 + 1][ix0] + wx1 * ms[c][iy0 + 1][ix0 + 1];
    op[(size_t)c << 18] = v + wy0 * a + wy1 * bb;
  }
}

extern "C" void kernel_launch(void* const* d_in, const int* in_sizes, int n_in,
                              void* d_out, int out_size) {
  const float* x    = (const float*)d_in[0];
  const float* w    = (const float*)d_in[1];
  const float* bias = (const float*)d_in[2];
  const float* uw   = (const float*)d_in[3];
  const float* pw   = (const float*)d_in[4];
  float* out = (float*)d_out;
  (void)in_sizes; (void)n_in; (void)out_size;

  dim3 b32x8(32, 8);
  k_conv<<<dim3(16, 64, 2), b32x8>>>(x, w, bias);
  k_poolrgb<<<384, 256>>>(x);
  k_kernels<<<dim3(4, 16, 2), b32x8>>>(pw);
  k_softpool<false><<<dim3(16, 64, 2), b32x8>>>(uw);
  for (int t = 0; t < 5; t++) {
    k_pac<<<dim3(1, 32, 8), b32x8>>>();
    if (t < 4) k_softpool<true><<<dim3(16, 64, 2), b32x8>>>(uw);
    else       k_final<<<dim3(16, 64, 2), b32x8>>>(uw, out);
  }
}

// round 7
// speedup vs baseline: 1.4026x; 1.0272x over previous
#include <cuda_runtime.h>

// ---------------- problem constants ----------------
// B=2, C=21, H=W=512, pooled 128x128, K=11 (radius 5), 5 steps, pad=(0,0)

// ---------------- scratch (device globals; no mallocs allowed) ----------------
__device__ float g_unary[11010048];   // [2][21][512][512]
__device__ float g_qb[688128];        // [2][21][128][128]
__device__ float g_msgp[2752512];     // [4 tap-groups][2][21][128][128] partial messages
__device__ float g_kcomb[3964928];    // [2][121][128][128]  (j-major)
__device__ float g_rgbp[98304];       // [2][3][128][128]    (already /13)

// ---------------- 4x4 avg-pool of x, folded /13 ----------------
__global__ void k_poolrgb(const float* __restrict__ x) {
  int idx = blockIdx.x * 256 + threadIdx.x;  // over 2*3*128*128
  if (idx >= 98304) return;
  int xp = idx & 127, yp = (idx >> 7) & 127, c = idx >> 14;  // c = b*3+ch
  const float* p = x + ((size_t)c << 18) + ((yp * 4) << 9) + (xp * 4);
  float s = 0.f;
#pragma unroll
  for (int i = 0; i < 4; i++)
#pragma unroll
    for (int j = 0; j < 4; j++) s += p[(i << 9) + j];
  g_rgbp[idx] = s * (1.0f / 208.0f);  // /16 pool, /13 feature scale
}

// ---------------- combined pairwise kernel: w1*bilateral + w2*spatial ----------------
__global__ void k_kernels(const float* __restrict__ pw) {
  __shared__ float rs[3][18][42];
  __shared__ float sA[121], sS[121];
  const int b  = blockIdx.z;
  const int x0 = blockIdx.x * 32, y0 = blockIdx.y * 8;
  const int tx = threadIdx.x, ty = threadIdx.y;
  const int tid = ty * 32 + tx;
  if (tid < 121) {
    int dy = tid / 11 - 5, dx = tid % 11 - 5;
    float d2 = (float)(dy * dy + dx * dx);
    sA[tid] = __expf(-d2 * (1.0f / 800.0f));  // pooled YX/80: (4d/80)^2/2
    sS[tid] = __expf(-d2 * (8.0f / 9.0f));    // pooled YX/3 : (4d/3)^2/2
  }
  for (int i = tid; i < 3 * 18 * 42; i += 256) {
    int c = i / 756, rem = i % 756, yy = rem / 42, xx = rem % 42;
    int gy = y0 + yy - 5, gx = x0 + xx - 5;
    float v = 0.f;
    if (gy >= 0 && gy < 128 && gx >= 0 && gx < 128)
      v = g_rgbp[((b * 3 + c) << 14) + (gy << 7) + gx];
    rs[c][yy][xx] = v;
  }
  __syncthreads();
  const float w1 = pw[0], w2 = pw[1];
  const float r0 = rs[0][ty + 5][tx + 5];
  const float r1 = rs[1][ty + 5][tx + 5];
  const float r2 = rs[2][ty + 5][tx + 5];
  const int y = y0 + ty, xg = x0 + tx;
  float* outp = g_kcomb + ((size_t)b * 121 << 14) + (y << 7) + xg;
  for (int dy = 0; dy < 11; dy++) {
    for (int dx = 0; dx < 11; dx++) {
      int j = dy * 11 + dx;
      int ny = y + dy - 5, nx = xg + dx - 5;
      float val = 0.f;  // OOB entries multiply zero-padded Q patches -> store 0
      if (ny >= 0 && ny < 128 && nx >= 0 && nx < 128) {
        float a = rs[0][ty + dy][tx + dx] - r0;
        float bb = rs[1][ty + dy][tx + dx] - r1;
        float cc = rs[2][ty + dy][tx + dx] - r2;
        float d2 = a * a + bb * bb + cc * cc;
        val = fmaf(w1 * sA[j], __expf(-0.5f * d2), w2 * sS[j]);
      }
      outp[(size_t)j << 14] = val;
    }
  }
}

// ---------------- fused: conv(3->21) -> write unary -> softmax -> 4x4 pool ----------------
// block 32x8, grid (16,64,2)
__global__ void k_convsoft(const float* __restrict__ x, const float* __restrict__ w,
                           const float* __restrict__ bias, const float* __restrict__ uwp) {
  __shared__ float xs[3][10][34];
  __shared__ float ws[567];
  __shared__ float bs[21];
  __shared__ float ps[8][8][21];
  const int b  = blockIdx.z;
  const int x0 = blockIdx.x * 32, y0 = blockIdx.y * 8;
  const int tx = threadIdx.x, ty = threadIdx.y;
  const int tid = ty * 32 + tx;
  const float uw = uwp[0];
  for (int i = tid; i < 567; i += 256) ws[i] = w[i];
  if (tid < 21) bs[tid] = bias[tid];
  for (int i = tid; i < 3 * 10 * 34; i += 256) {
    int c = i / 340, rem = i % 340, yy = rem / 34, xx = rem % 34;
    int gy = y0 + yy - 1, gx = x0 + xx - 1;
    float v = 0.f;
    if (gy >= 0 && gy < 512 && gx >= 0 && gx < 512)
      v = x[((size_t)(b * 3 + c) << 18) + (gy << 9) + gx];
    xs[c][yy][xx] = v;
  }
  __syncthreads();
  float r[27];
#pragma unroll
  for (int c = 0; c < 3; c++)
#pragma unroll
    for (int ky = 0; ky < 3; ky++)
#pragma unroll
      for (int kx = 0; kx < 3; kx++)
        r[c * 9 + ky * 3 + kx] = xs[c][ty + ky][tx + kx];
  float* outp = g_unary + ((size_t)b * 21 << 18) + ((y0 + ty) << 9) + (x0 + tx);
  float logit[21];
  float mx = -1e30f;
#pragma unroll
  for (int o = 0; o < 21; o++) {
    float acc = bs[o];
#pragma unroll
    for (int i = 0; i < 27; i++) acc = fmaf(r[i], ws[o * 27 + i], acc);
    outp[(size_t)o << 18] = acc;
    float v = uw * acc;
    logit[o] = v;
    mx = fmaxf(mx, v);
  }
  float s = 0.f;
#pragma unroll
  for (int c = 0; c < 21; c++) { float e = __expf(logit[c] - mx); logit[c] = e; s += e; }
  float inv = __frcp_rn(s);
#pragma unroll
  for (int c = 0; c < 21; c++) {
    float q = logit[c] * inv;
    q += __shfl_down_sync(0xffffffffu, q, 1);
    q += __shfl_down_sync(0xffffffffu, q, 2);
    logit[c] = q;
  }
  if ((tx & 3) == 0) {
#pragma unroll
    for (int c = 0; c < 21; c++) ps[ty][tx >> 2][c] = logit[c];
  }
  __syncthreads();
  for (int i = tid; i < 336; i += 256) {
    int c = i % 21, pxx = (i / 21) & 7, pyy = i / 168;
    float sum = ps[pyy * 4 + 0][pxx][c] + ps[pyy * 4 + 1][pxx][c] +
                ps[pyy * 4 + 2][pxx][c] + ps[pyy * 4 + 3][pxx][c];
    int yp = (y0 >> 2) + pyy, xp = (x0 >> 2) + pxx;
    g_qb[((b * 21 + c) << 14) + (yp << 7) + xp] = sum * 0.0625f;
  }
}

// ---------------- fused: (uw*unary + upsample(msg)) -> softmax -> 4x4 pool ----------------
__global__ void k_softpool(const float* __restrict__ uwp) {
  __shared__ float ms[21][4][10];
  __shared__ float ps[8][8][21];
  const int b  = blockIdx.z;
  const int x0 = blockIdx.x * 32, y0 = blockIdx.y * 8;
  const int tx = threadIdx.x, ty = threadIdx.y;
  const int tid = ty * 32 + tx;
  const float uw = uwp[0];
  {
    int qx0 = (x0 >> 2) - 1, qy0 = (y0 >> 2) - 1;
    for (int i = tid; i < 21 * 4 * 10; i += 256) {
      int c = i / 40, rem = i % 40, yy = rem / 10, xx = rem % 10;
      int gy = min(max(qy0 + yy, 0), 127), gx = min(max(qx0 + xx, 0), 127);
      size_t idx = (size_t)((b * 21 + c) << 14) + (gy << 7) + gx;
      ms[c][yy][xx] = g_msgp[idx] + g_msgp[688128 + idx] +
                      g_msgp[2 * 688128 + idx] + g_msgp[3 * 688128 + idx];
    }
    __syncthreads();
  }
  const int pxp = tx & 3;
  const int ix0 = (tx >> 2) + (pxp >= 2 ? 1 : 0);
  const float wx0 = (pxp == 0) ? 0.375f : (pxp == 1) ? 0.125f : (pxp == 2) ? 0.875f : 0.625f;
  const float wx1 = 1.f - wx0;
  const int pyp = ty & 3;
  const int iy0 = (ty >> 2) + (pyp >= 2 ? 1 : 0);
  const float wy0 = (pyp == 0) ? 0.375f : (pyp == 1) ? 0.125f : (pyp == 2) ? 0.875f : 0.625f;
  const float wy1 = 1.f - wy0;
  const int y = y0 + ty, xg = x0 + tx;
  const float* up = g_unary + ((size_t)b * 21 << 18) + (y << 9) + xg;
  float logit[21];
  float mx = -1e30f;
#pragma unroll
  for (int c = 0; c < 21; c++) {
    float v = uw * up[(size_t)c << 18];
    float a  = wx0 * ms[c][iy0][ix0]     + wx1 * ms[c][iy0][ix0 + 1];
    float bb = wx0 * ms[c][iy0 + 1][ix0] + wx1 * ms[c][iy0 + 1][ix0 + 1];
    v += wy0 * a + wy1 * bb;
    logit[c] = v;
    mx = fmaxf(mx, v);
  }
  float s = 0.f;
#pragma unroll
  for (int c = 0; c < 21; c++) { float e = __expf(logit[c] - mx); logit[c] = e; s += e; }
  float inv = __frcp_rn(s);
#pragma unroll
  for (int c = 0; c < 21; c++) {
    float q = logit[c] * inv;
    q += __shfl_down_sync(0xffffffffu, q, 1);
    q += __shfl_down_sync(0xffffffffu, q, 2);
    logit[c] = q;
  }
  if ((tx & 3) == 0) {
#pragma unroll
    for (int c = 0; c < 21; c++) ps[ty][tx >> 2][c] = logit[c];
  }
  __syncthreads();
  for (int i = tid; i < 336; i += 256) {
    int c = i % 21, pxx = (i / 21) & 7, pyy = i / 168;
    float sum = ps[pyy * 4 + 0][pxx][c] + ps[pyy * 4 + 1][pxx][c] +
                ps[pyy * 4 + 2][pxx][c] + ps[pyy * 4 + 3][pxx][c];
    int yp = (y0 >> 2) + pyy, xp = (x0 >> 2) + pxx;
    g_qb[((b * 21 + c) << 14) + (yp << 7) + xp] = sum * 0.0625f;
  }
}

// ---------------- pixel-adaptive 11x11 message at 128x128 ----------------
// x4-vectorized, tap-split x4, 64-wide blocks for residency: smem 42.2KB,
// 128 thr, 4 blocks/SM. Block covers 64 px x 4 rows; ty&3 = row, ty>>2 =
// channel group (0: c0..10, 1: c11..20+pad). grid (2,32,8), z = b*4+g,
// tap rows [3g,3g+3) (g=3: [9,11)).
__global__ __launch_bounds__(128, 4) void k_pac() {
  __shared__ float qs[22][6][80];   // ch 21 = zero pad (keeps loops uniform)
  const int bz = blockIdx.z;
  const int b  = bz >> 2, g = bz & 3;
  const int s  = g * 3;
  const int nrr = (g == 3) ? 2 : 3;
  const int x0 = blockIdx.x * 64;
  const int y0 = blockIdx.y * 4;
  const int tx = threadIdx.x;            // 0..15
  const int ty = threadIdx.y & 3;        // output row within strip
  const int tz = threadIdx.y >> 2;       // channel group
  const int tid = threadIdx.y * 16 + tx;
  const int qy0 = y0 - 5 + s;
  for (int i = tid; i < 22 * 6 * 80; i += 128) {
    int c = i / 480, rem = i % 480, r = rem / 80, xx = rem % 80;
    int gy = qy0 + r, gx = x0 - 5 + xx;
    float v = 0.f;
    if (c < 21 && xx < 74 && gy >= 0 && gy < 128 && gx >= 0 && gx < 128)
      v = g_qb[((b * 21 + c) << 14) + (gy << 7) + gx];
    qs[c][r][xx] = v;
  }
  __syncthreads();
  const int c0 = tz * 11;
  const int y  = y0 + ty;
  const int xb = tx * 4;
  float acc[11][4];
#pragma unroll
  for (int c = 0; c < 11; c++)
#pragma unroll
    for (int o = 0; o < 4; o++) acc[c][o] = 0.f;
  const float* kbase = g_kcomb + ((size_t)b * 121 << 14) + (y << 7) + x0 + xb;
  for (int rr = s; rr < s + nrr; rr++) {
    float4 kv[11];
#pragma unroll
    for (int dx = 0; dx < 11; dx++)
      kv[dx] = __ldg(reinterpret_cast<const float4*>(kbase + ((size_t)(rr * 11 + dx) << 14)));
    const int r = ty + rr - s;   // smem row index
#pragma unroll
    for (int c = 0; c < 11; c++) {
      const float4* qp = reinterpret_cast<const float4*>(&qs[c0 + c][r][xb]);
      float4 q0 = qp[0], q1 = qp[1], q2 = qp[2], q3 = qp[3];
      float qf[16] = {q0.x, q0.y, q0.z, q0.w, q1.x, q1.y, q1.z, q1.w,
                      q2.x, q2.y, q2.z, q2.w, q3.x, q3.y, q3.z, q3.w};
#pragma unroll
      for (int dx = 0; dx < 11; dx++) {
        acc[c][0] = fmaf(kv[dx].x, qf[dx + 0], acc[c][0]);
        acc[c][1] = fmaf(kv[dx].y, qf[dx + 1], acc[c][1]);
        acc[c][2] = fmaf(kv[dx].z, qf[dx + 2], acc[c][2]);
        acc[c][3] = fmaf(kv[dx].w, qf[dx + 3], acc[c][3]);
      }
    }
  }
  float* mp = g_msgp + (size_t)g * 688128 + ((size_t)(b * 21 + c0) << 14) + (y << 7) + x0 + xb;
#pragma unroll
  for (int c = 0; c < 11; c++) {
    if (c0 + c < 21) {
      float4 v = make_float4(acc[c][0], acc[c][1], acc[c][2], acc[c][3]);
      *reinterpret_cast<float4*>(mp + ((size_t)c << 14)) = v;
    }
  }
}

// ---------------- last step: logQ = uw*unary + upsample(msg) -> d_out ----------------
__global__ void k_final(const float* __restrict__ uwp, float* __restrict__ out) {
  __shared__ float ms[21][4][10];
  const int b  = blockIdx.z;
  const int x0 = blockIdx.x * 32, y0 = blockIdx.y * 8;
  const int tx = threadIdx.x, ty = threadIdx.y;
  const int tid = ty * 32 + tx;
  const float uw = uwp[0];
  {
    int qx0 = (x0 >> 2) - 1, qy0 = (y0 >> 2) - 1;
    for (int i = tid; i < 21 * 4 * 10; i += 256) {
      int c = i / 40, rem = i % 40, yy = rem / 10, xx = rem % 10;
      int gy = min(max(qy0 + yy, 0), 127), gx = min(max(qx0 + xx, 0), 127);
      size_t idx = (size_t)((b * 21 + c) << 14) + (gy << 7) + gx;
      ms[c][yy][xx] = g_msgp[idx] + g_msgp[688128 + idx] +
                      g_msgp[2 * 688128 + idx] + g_msgp[3 * 688128 + idx];
    }
    __syncthreads();
  }
  const int pxp = tx & 3;
  const int ix0 = (tx >> 2) + (pxp >= 2 ? 1 : 0);
  const float wx0 = (pxp == 0) ? 0.375f : (pxp == 1) ? 0.125f : (pxp == 2) ? 0.875f : 0.625f;
  const float wx1 = 1.f - wx0;
  const int pyp = ty & 3;
  const int iy0 = (ty >> 2) + (pyp >= 2 ? 1 : 0);
  const float wy0 = (pyp == 0) ? 0.375f : (pyp == 1) ? 0.125f : (pyp == 2) ? 0.875f : 0.625f;
  const float wy1 = 1.f - wy0;
  const int y = y0 + ty, xg = x0 + tx;
  const float* up = g_unary + ((size_t)b * 21 << 18) + (y << 9) + xg;
  float* op = out + ((size_t)b * 21 << 18) + (y << 9) + xg;
#pragma unroll
  for (int c = 0; c < 21; c++) {
    float v = uw * up[(size_t)c << 18];
    float a  = wx0 * ms[c][iy0][ix0]     + wx1 * ms[c][iy0][ix0 + 1];
    float bb = wx0 * ms[c][iy0 + 1][ix0] + wx1 * ms[c][iy0 + 1][ix0 + 1];
    op[(size_t)c << 18] = v + wy0 * a + wy1 * bb;
  }
}

extern "C" void kernel_launch(void* const* d_in, const int* in_sizes, int n_in,
                              void* d_out, int out_size) {
  const float* x    = (const float*)d_in[0];
  const float* w    = (const float*)d_in[1];
  const float* bias = (const float*)d_in[2];
  const float* uw   = (const float*)d_in[3];
  const float* pw   = (const float*)d_in[4];
  float* out = (float*)d_out;
  (void)in_sizes; (void)n_in; (void)out_size;

  dim3 b32x8(32, 8);
  k_poolrgb<<<384, 256>>>(x);
  k_kernels<<<dim3(4, 16, 2), b32x8>>>(pw);
  k_convsoft<<<dim3(16, 64, 2), b32x8>>>(x, w, bias, uw);
  for (int t = 0; t < 5; t++) {
    k_pac<<<dim3(2, 32, 8), dim3(16, 8)>>>();
    if (t < 4) k_softpool<<<dim3(16, 64, 2), b32x8>>>(uw);
    else       k_final<<<dim3(16, 64, 2), b32x8>>>(uw, out);
  }
}